// round 6
// baseline (speedup 1.0000x reference)
#include <cuda_runtime.h>
#include <cstddef>
#include <cstdint>

// LocalAttention: B=4, S=2048, D=256, W=33
// out = [values (B,S,D) | p_attn (B,S,W)] as float32

#define S_LEN   2048
#define D_DIM   256
#define B_SZ    4
#define W_SZ    33
#define HALF_W  16
#define TILE_Q  32
#define THREADS 512                // 16 warps
#define QW      2                  // queries per warp
#define ROWS    (TILE_Q + 2*HALF_W)  // 64 K/V rows in smem (shared K/V buffer)
#define D4      (D_DIM/4)          // 64 16B-chunks per row
#define NR      (QW + 2*HALF_W)    // 34 rows per warp

// smem: KV buffer (reused: K then V) + scores + flags
#define SMEM_BYTES (ROWS*D_DIM*4 + TILE_Q*W_SZ*4 + ROWS*4)

typedef unsigned long long ull;

__device__ __forceinline__ ull fma2(ull a, ull b, ull c) {
    ull d;
    asm("fma.rn.f32x2 %0, %1, %2, %3;" : "=l"(d) : "l"(a), "l"(b), "l"(c));
    return d;
}
__device__ __forceinline__ float f32x2_sum(ull v) {
    float lo, hi;
    asm("mov.b64 {%0, %1}, %2;" : "=f"(lo), "=f"(hi) : "l"(v));
    return lo + hi;
}
__device__ __forceinline__ ull pack2(float x) {
    ull d;
    asm("mov.b64 %0, {%1, %1};" : "=l"(d) : "f"(x));
    return d;
}
__device__ __forceinline__ void cp16(void* smem_dst, const void* gsrc) {
    uint32_t s = (uint32_t)__cvta_generic_to_shared(smem_dst);
    asm volatile("cp.async.cg.shared.global [%0], [%1], 16;" :: "r"(s), "l"(gsrc));
}

__global__ void __launch_bounds__(THREADS, 2)
local_attn_kernel(const float* __restrict__ qg,
                  const float* __restrict__ kg,
                  const float* __restrict__ vg,
                  const int*   __restrict__ maskg,
                  float* __restrict__ out_vals,
                  float* __restrict__ out_p)
{
    extern __shared__ float smem[];
    float4* KVsm = reinterpret_cast<float4*>(smem);                 // [ROWS][D4]
    float*  Ssm  = reinterpret_cast<float*>(KVsm + ROWS * D4);      // [TILE_Q][W_SZ]
    int*    Fsm  = reinterpret_cast<int*>(Ssm + TILE_Q * W_SZ);     // [ROWS]

    const int tile = blockIdx.x;           // 0..63
    const int b    = blockIdx.y;           // 0..3
    const int base = tile * TILE_Q;
    const int r0   = base - HALF_W;
    const int tid  = threadIdx.x;

    const float4* kg4 = reinterpret_cast<const float4*>(kg + (size_t)b * S_LEN * D_DIM);
    const float4* vg4 = reinterpret_cast<const float4*>(vg + (size_t)b * S_LEN * D_DIM);

    // ---- async-stage K into shared KV buffer ----
    #pragma unroll
    for (int it = 0; it < ROWS * D4 / THREADS; ++it) {   // 8 iters
        int idx  = tid + it * THREADS;
        int row  = idx >> 6;
        int col  = idx & (D4 - 1);
        int grow = r0 + row;
        int gcl  = grow < 0 ? 0 : (grow >= S_LEN ? S_LEN - 1 : grow);
        cp16(KVsm + idx, kg4 + (size_t)gcl * D4 + col);
    }
    asm volatile("cp.async.commit_group;" ::: "memory");

    // ---- mask flags ----
    if (tid < ROWS) {
        int grow = r0 + tid;
        int f = 0;
        if (grow >= 0 && grow < S_LEN) f = (maskg[b * S_LEN + grow] != 0);
        Fsm[tid] = f;
    }

    const int warp = tid >> 5;       // 0..15
    const int lane = tid & 31;
    const int lq0  = warp * QW;      // warp's first local query (0..30, step 2)

    // pass-1 lane decomposition: h = row of pair, p = 16-lane d-position
    const int h = lane >> 4;
    const int p = lane & 15;

    // ---- Q fragments: both queries, 4 chunks each (overlaps cp.async drain) ----
    ulonglong2 qf[QW][4];
    {
        const ulonglong2* qb = reinterpret_cast<const ulonglong2*>(
            qg + ((size_t)b * S_LEN + base + lq0) * D_DIM);
        #pragma unroll
        for (int q = 0; q < QW; ++q)
            #pragma unroll
            for (int c = 0; c < 4; ++c)
                qf[q][c] = qb[q * D4 + p + 16 * c];
    }

    asm volatile("cp.async.wait_group 0;" ::: "memory");
    __syncthreads();

    const ulonglong2* Ksm2 = reinterpret_cast<const ulonglong2*>(KVsm);
    float* swarp = Ssm + lq0 * W_SZ;

    // ---- pass 1: scores, two rows per iteration ----
    #pragma unroll 2
    for (int ri = 0; ri < NR / 2; ++ri) {   // 17 iters
        int m = lq0 + 2 * ri + h;
        const ulonglong2* krow = Ksm2 + m * D4 + p;

        ull a0q0 = 0ull, a1q0 = 0ull, a0q1 = 0ull, a1q1 = 0ull;
        #pragma unroll
        for (int c = 0; c < 4; ++c) {
            ulonglong2 kk = krow[16 * c];
            a0q0 = fma2(kk.x, qf[0][c].x, a0q0);
            a1q0 = fma2(kk.y, qf[0][c].y, a1q0);
            a0q1 = fma2(kk.x, qf[1][c].x, a0q1);
            a1q1 = fma2(kk.y, qf[1][c].y, a1q1);
        }
        float s0 = f32x2_sum(a0q0) + f32x2_sum(a1q0);
        float s1 = f32x2_sum(a0q1) + f32x2_sum(a1q1);

        // reduce over the 16 d-lanes of this half
        s0 += __shfl_xor_sync(0xffffffffu, s0, 8);
        s1 += __shfl_xor_sync(0xffffffffu, s1, 8);
        s0 += __shfl_xor_sync(0xffffffffu, s0, 4);
        s1 += __shfl_xor_sync(0xffffffffu, s1, 4);
        // select query by bit2 of p, finish over bits 0,1
        float v = ((p >> 2) & 1) ? s1 : s0;
        v += __shfl_xor_sync(0xffffffffu, v, 2);
        v += __shfl_xor_sync(0xffffffffu, v, 1);

        int rl = 2 * ri + h;
        int g  = (p >> 2) & 1;          // query this lane carries
        int wpos = rl - g;
        bool writer = ((p & 0xB) == 0); // p == 0 (q0) or p == 4 (q1)
        if (writer && wpos >= 0 && wpos < W_SZ) {
            float sc = Fsm[m] ? v * 0.0625f : -1e10f;   // * 1/sqrt(256)
            swarp[g * W_SZ + wpos] = sc;
        }
    }
    __syncthreads();   // all warps done reading K from the shared buffer

    // ---- async-stage V into the same buffer; softmax overlaps the flight ----
    #pragma unroll
    for (int it = 0; it < ROWS * D4 / THREADS; ++it) {   // 8 iters
        int idx  = tid + it * THREADS;
        int row  = idx >> 6;
        int col  = idx & (D4 - 1);
        int grow = r0 + row;
        int gcl  = grow < 0 ? 0 : (grow >= S_LEN ? S_LEN - 1 : grow);
        cp16(KVsm + idx, vg4 + (size_t)gcl * D4 + col);
    }
    asm volatile("cp.async.commit_group;" ::: "memory");

    // ---- warp-local softmax: 16 lanes per query ----
    const int gq16 = lane >> 4;        // which of the warp's 2 queries
    const int j    = lane & 15;
    const int lq   = lq0 + gq16;
    const int gq   = base + lq;
    float* srow = Ssm + lq * W_SZ;
    {
        float s0 = srow[j];
        float s1 = srow[j + 16];
        float s2 = (j == 0) ? srow[32] : -3e38f;

        float mx = fmaxf(fmaxf(s0, s1), s2);
        mx = fmaxf(mx, __shfl_xor_sync(0xffffffffu, mx, 8));
        mx = fmaxf(mx, __shfl_xor_sync(0xffffffffu, mx, 4));
        mx = fmaxf(mx, __shfl_xor_sync(0xffffffffu, mx, 2));
        mx = fmaxf(mx, __shfl_xor_sync(0xffffffffu, mx, 1));

        float e0 = __expf(s0 - mx);
        float e1 = __expf(s1 - mx);
        float e2 = (j == 0) ? __expf(s2 - mx) : 0.f;

        float sum = (e0 + e1) + e2;
        sum += __shfl_xor_sync(0xffffffffu, sum, 8);
        sum += __shfl_xor_sync(0xffffffffu, sum, 4);
        sum += __shfl_xor_sync(0xffffffffu, sum, 2);
        sum += __shfl_xor_sync(0xffffffffu, sum, 1);
        float inv = 1.f / sum;

        float p0 = e0 * inv, p1 = e1 * inv;
        srow[j]      = p0;
        srow[j + 16] = p1;

        float* po = out_p + (size_t)(b * S_LEN + gq) * W_SZ;
        po[j]      = p0;
        po[j + 16] = p1;
        if (j == 0) {
            float p2v = e2 * inv;
            srow[32] = p2v;
            po[32]   = p2v;
        }
    }

    asm volatile("cp.async.wait_group 0;" ::: "memory");
    __syncthreads();   // V resident + visible, scores final

    // ---- pass 2: lane owns 32B d-slice at chunk 2*lane ----
    ulonglong2 acc[QW][2];
    #pragma unroll
    for (int q = 0; q < QW; ++q) {
        acc[q][0].x = 0ull; acc[q][0].y = 0ull;
        acc[q][1].x = 0ull; acc[q][1].y = 0ull;
    }

    const ulonglong2* Vsm2 = reinterpret_cast<const ulonglong2*>(KVsm);
    const float* sbase = Ssm + lq0 * W_SZ;
    #pragma unroll 2
    for (int r = 0; r < NR; ++r) {   // 34
        int m = lq0 + r;
        const ulonglong2* vrow = Vsm2 + m * D4 + 2 * lane;
        ulonglong2 v0 = vrow[0];
        ulonglong2 v1 = vrow[1];
        #pragma unroll
        for (int q = 0; q < QW; ++q) {
            int wpos = r - q;
            float pv = (wpos >= 0 && wpos < W_SZ) ? sbase[q * W_SZ + wpos] : 0.f;
            ull pp = pack2(pv);
            acc[q][0].x = fma2(pp, v0.x, acc[q][0].x);
            acc[q][0].y = fma2(pp, v0.y, acc[q][0].y);
            acc[q][1].x = fma2(pp, v1.x, acc[q][1].x);
            acc[q][1].y = fma2(pp, v1.y, acc[q][1].y);
        }
    }

    ulonglong2* obase = reinterpret_cast<ulonglong2*>(
        out_vals + ((size_t)b * S_LEN + base + lq0) * D_DIM);
    #pragma unroll
    for (int q = 0; q < QW; ++q) {
        obase[q * D4 + 2 * lane]     = acc[q][0];
        obase[q * D4 + 2 * lane + 1] = acc[q][1];
    }
}

extern "C" void kernel_launch(void* const* d_in, const int* in_sizes, int n_in,
                              void* d_out, int out_size)
{
    const float* q    = (const float*)d_in[0];
    const float* k    = (const float*)d_in[1];
    const float* v    = (const float*)d_in[2];
    const int*   mask = (const int*)d_in[3];

    float* out_vals = (float*)d_out;
    float* out_p    = out_vals + (size_t)B_SZ * S_LEN * D_DIM;

    static bool attr_set = false;
    if (!attr_set) {
        cudaFuncSetAttribute(local_attn_kernel,
                             cudaFuncAttributeMaxDynamicSharedMemorySize,
                             SMEM_BYTES);
        attr_set = true;
    }

    dim3 grid(S_LEN / TILE_Q, B_SZ);   // (64, 4) = 256 CTAs
    local_attn_kernel<<<grid, THREADS, SMEM_BYTES>>>(q, k, v, mask, out_vals, out_p);
}

// round 9
// speedup vs baseline: 1.4407x; 1.4407x over previous
#include <cuda_runtime.h>
#include <cstddef>
#include <cstdint>

// LocalAttention: B=4, S=2048, D=256, W=33
// out = [values (B,S,D) | p_attn (B,S,W)] as float32

#define S_LEN   2048
#define D_DIM   256
#define B_SZ    4
#define W_SZ    33
#define HALF_W  16
#define TILE_Q  64
#define THREADS 512                // 16 warps
#define QW      4                  // queries per warp
#define ROWS    (TILE_Q + 2*HALF_W)  // 96 K/V rows in smem
#define D4      (D_DIM/4)          // 64 16B-chunks per row
#define NR      (QW + 2*HALF_W)    // 36 rows per warp
#define NW      (THREADS/32)       // 16 warps

// smem: K tile + V tile + transposed scores [16 warps][NR][4] + flags
#define S2_PER_WARP (NR*4)         // 144 floats
#define SMEM_BYTES (ROWS*D_DIM*4*2 + NW*S2_PER_WARP*4 + ROWS*4)

typedef unsigned long long ull;

__device__ __forceinline__ ull fma2(ull a, ull b, ull c) {
    ull d;
    asm("fma.rn.f32x2 %0, %1, %2, %3;" : "=l"(d) : "l"(a), "l"(b), "l"(c));
    return d;
}
__device__ __forceinline__ float f32x2_sum(ull v) {
    float lo, hi;
    asm("mov.b64 {%0, %1}, %2;" : "=f"(lo), "=f"(hi) : "l"(v));
    return lo + hi;
}
__device__ __forceinline__ ull pack2(float x) {
    ull d;
    asm("mov.b64 %0, {%1, %1};" : "=l"(d) : "f"(x));
    return d;
}
__device__ __forceinline__ void cp16(void* smem_dst, const void* gsrc) {
    uint32_t s = (uint32_t)__cvta_generic_to_shared(smem_dst);
    asm volatile("cp.async.cg.shared.global [%0], [%1], 16;" :: "r"(s), "l"(gsrc));
}

__global__ void __launch_bounds__(THREADS, 1)
local_attn_kernel(const float* __restrict__ qg,
                  const float* __restrict__ kg,
                  const float* __restrict__ vg,
                  const int*   __restrict__ maskg,
                  float* __restrict__ out_vals,
                  float* __restrict__ out_p)
{
    extern __shared__ float smem[];
    float4* Ksm = reinterpret_cast<float4*>(smem);
    float4* Vsm = Ksm + ROWS * D4;
    float*  S2  = reinterpret_cast<float*>(Vsm + ROWS * D4);   // [NW][NR][4]
    int*    Fsm = reinterpret_cast<int*>(S2 + NW * S2_PER_WARP); // [ROWS]

    const int tile = blockIdx.x;
    const int b    = blockIdx.y;
    const int base = tile * TILE_Q;
    const int r0   = base - HALF_W;
    const int tid  = threadIdx.x;

    const float4* kg4 = reinterpret_cast<const float4*>(kg + (size_t)b * S_LEN * D_DIM);
    const float4* vg4 = reinterpret_cast<const float4*>(vg + (size_t)b * S_LEN * D_DIM);

    // ---- async-stage K (group 0) ----
    #pragma unroll
    for (int it = 0; it < ROWS * D4 / THREADS; ++it) {   // 12 iters
        int idx  = tid + it * THREADS;
        int row  = idx >> 6;
        int col  = idx & (D4 - 1);
        int grow = r0 + row;
        int gcl  = grow < 0 ? 0 : (grow >= S_LEN ? S_LEN - 1 : grow);
        cp16(Ksm + idx, kg4 + (size_t)gcl * D4 + col);
    }
    asm volatile("cp.async.commit_group;" ::: "memory");

    // ---- async-stage V (group 1; waited before pass 2) ----
    #pragma unroll
    for (int it = 0; it < ROWS * D4 / THREADS; ++it) {
        int idx  = tid + it * THREADS;
        int row  = idx >> 6;
        int col  = idx & (D4 - 1);
        int grow = r0 + row;
        int gcl  = grow < 0 ? 0 : (grow >= S_LEN ? S_LEN - 1 : grow);
        cp16(Vsm + idx, vg4 + (size_t)gcl * D4 + col);
    }
    asm volatile("cp.async.commit_group;" ::: "memory");

    // ---- mask flags + zero score pads (during cp.async flight) ----
    if (tid < ROWS) {
        int grow = r0 + tid;
        int f = 0;
        if (grow >= 0 && grow < S_LEN) f = (maskg[b * S_LEN + grow] != 0);
        Fsm[tid] = f;
    }

    const int warp = tid >> 5;
    const int lane = tid & 31;
    const int lq0  = warp * QW;
    float* s2w = S2 + warp * S2_PER_WARP;    // this warp's [NR][4] scores

    // zero this warp's score block (covers out-of-window slots read by pass 2)
    #pragma unroll
    for (int i = lane; i < S2_PER_WARP; i += 32) s2w[i] = 0.f;

    // pass-1 lane decomposition: h = row of pair, p = 16-lane d-position
    const int h  = lane >> 4;
    const int p  = lane & 15;
    const int b3 = (p >> 3) & 1;
    const int b2 = (p >> 2) & 1;
    const int qcar = (b2 << 1) | b3;          // query this lane carries after reduce

    // ---- Q fragments (LDG overlaps the cp.async drain) ----
    ulonglong2 qf[QW][4];
    {
        const ulonglong2* qb = reinterpret_cast<const ulonglong2*>(
            qg + ((size_t)b * S_LEN + base + lq0) * D_DIM);
        #pragma unroll
        for (int q = 0; q < QW; ++q)
            #pragma unroll
            for (int c = 0; c < 4; ++c)
                qf[q][c] = qb[q * D4 + p + 16 * c];
    }

    // wait for K (V still in flight), then block-sync (also orders s2w zeroing)
    asm volatile("cp.async.wait_group 1;" ::: "memory");
    __syncthreads();

    const ulonglong2* Ksm2 = reinterpret_cast<const ulonglong2*>(Ksm);

    // ---- pass 1: scores, two rows per iteration, 5-shfl pair-compressed reduce ----
    #pragma unroll 2
    for (int ri = 0; ri < NR / 2; ++ri) {   // 18 iters
        int m = lq0 + 2 * ri + h;
        const ulonglong2* krow = Ksm2 + m * D4 + p;
        ulonglong2 k0 = krow[0];
        ulonglong2 k1 = krow[16];
        ulonglong2 k2 = krow[32];
        ulonglong2 k3 = krow[48];

        float s[QW];
        #pragma unroll
        for (int q = 0; q < QW; ++q) {
            ull a0 = fma2(k0.x, qf[q][0].x, 0ull);
            ull a1 = fma2(k0.y, qf[q][0].y, 0ull);
            a0 = fma2(k1.x, qf[q][1].x, a0);
            a1 = fma2(k1.y, qf[q][1].y, a1);
            a0 = fma2(k2.x, qf[q][2].x, a0);
            a1 = fma2(k2.y, qf[q][2].y, a1);
            a0 = fma2(k3.x, qf[q][3].x, a0);
            a1 = fma2(k3.y, qf[q][3].y, a1);
            s[q] = f32x2_sum(a0) + f32x2_sum(a1);
        }

        // level xor8 (bit3): pair (s0,s1) and (s2,s3)
        float xA_keep = b3 ? s[1] : s[0];
        float xA_send = b3 ? s[0] : s[1];
        float xB_keep = b3 ? s[3] : s[2];
        float xB_send = b3 ? s[2] : s[3];
        float xA = xA_keep + __shfl_xor_sync(0xffffffffu, xA_send, 8);
        float xB = xB_keep + __shfl_xor_sync(0xffffffffu, xB_send, 8);
        // level xor4 (bit2): pair (xA, xB)
        float z_keep = b2 ? xB : xA;
        float z_send = b2 ? xA : xB;
        float z = z_keep + __shfl_xor_sync(0xffffffffu, z_send, 4);
        // levels xor2, xor1: same query both sides
        z += __shfl_xor_sync(0xffffffffu, z, 2);
        z += __shfl_xor_sync(0xffffffffu, z, 1);
        // lane p in {0,4,8,12} holds query qcar fully reduced over its half

        int rl = 2 * ri + h;
        int wpos = rl - qcar;
        if ((p & 3) == 0 && wpos >= 0 && wpos < W_SZ) {
            float sc = Fsm[m] ? z * 0.0625f : -1e10f;   // * 1/sqrt(256)
            s2w[rl * 4 + qcar] = sc;
        }
    }
    __syncwarp();

    // ---- warp-local softmax: 8 lanes per query; scores at s2w[(g8+w)*4+g8] ----
    const int g8 = lane >> 3;
    const int j  = lane & 7;
    const int gq = base + lq0 + g8;
    {
        float s0 = s2w[(g8 + j) * 4 + g8];
        float s1 = s2w[(g8 + j + 8) * 4 + g8];
        float s2v = s2w[(g8 + j + 16) * 4 + g8];
        float s3 = s2w[(g8 + j + 24) * 4 + g8];
        float s4 = (j == 0) ? s2w[(g8 + 32) * 4 + g8] : -3e38f;

        float mx = fmaxf(fmaxf(fmaxf(s0, s1), fmaxf(s2v, s3)), s4);
        mx = fmaxf(mx, __shfl_xor_sync(0xffffffffu, mx, 4));
        mx = fmaxf(mx, __shfl_xor_sync(0xffffffffu, mx, 2));
        mx = fmaxf(mx, __shfl_xor_sync(0xffffffffu, mx, 1));

        float e0 = __expf(s0 - mx);
        float e1 = __expf(s1 - mx);
        float e2 = __expf(s2v - mx);
        float e3 = __expf(s3 - mx);
        float e4 = (j == 0) ? __expf(s4 - mx) : 0.f;

        float sum = ((e0 + e1) + (e2 + e3)) + e4;
        sum += __shfl_xor_sync(0xffffffffu, sum, 4);
        sum += __shfl_xor_sync(0xffffffffu, sum, 2);
        sum += __shfl_xor_sync(0xffffffffu, sum, 1);
        float inv = 1.f / sum;

        float p0 = e0 * inv, p1 = e1 * inv, p2 = e2 * inv, p3 = e3 * inv;
        s2w[(g8 + j) * 4 + g8]      = p0;
        s2w[(g8 + j + 8) * 4 + g8]  = p1;
        s2w[(g8 + j + 16) * 4 + g8] = p2;
        s2w[(g8 + j + 24) * 4 + g8] = p3;

        float* po = out_p + (size_t)(b * S_LEN + gq) * W_SZ;
        po[j]      = p0;
        po[j + 8]  = p1;
        po[j + 16] = p2;
        po[j + 24] = p3;
        if (j == 0) {
            float p4 = e4 * inv;
            s2w[(g8 + 32) * 4 + g8] = p4;
            po[32]   = p4;
        }
    }

    // V must be resident + visible block-wide before pass 2
    asm volatile("cp.async.wait_group 0;" ::: "memory");
    __syncthreads();

    // ---- pass 2: one broadcast LDS.128 per row gives p for all 4 queries ----
    ulonglong2 acc[QW][2];
    #pragma unroll
    for (int q = 0; q < QW; ++q) {
        acc[q][0].x = 0ull; acc[q][0].y = 0ull;
        acc[q][1].x = 0ull; acc[q][1].y = 0ull;
    }

    const ulonglong2* Vsm2 = reinterpret_cast<const ulonglong2*>(Vsm);
    const float4* s2v4 = reinterpret_cast<const float4*>(s2w);

    ulonglong2 v0 = Vsm2[(size_t)lq0 * D4 + 2 * lane];
    ulonglong2 v1 = Vsm2[(size_t)lq0 * D4 + 2 * lane + 1];

    #pragma unroll 4
    for (int r = 0; r < NR; ++r) {   // 36
        ulonglong2 v0n, v1n;
        if (r + 1 < NR) {
            const ulonglong2* vn = Vsm2 + (size_t)(lq0 + r + 1) * D4 + 2 * lane;
            v0n = vn[0];
            v1n = vn[1];
        }
        float4 pv = s2v4[r];     // p for queries 0..3 at this row (0 if out of window)
        ull pp0 = pack2(pv.x);
        ull pp1 = pack2(pv.y);
        ull pp2 = pack2(pv.z);
        ull pp3 = pack2(pv.w);
        acc[0][0].x = fma2(pp0, v0.x, acc[0][0].x);
        acc[0][0].y = fma2(pp0, v0.y, acc[0][0].y);
        acc[0][1].x = fma2(pp0, v1.x, acc[0][1].x);
        acc[0][1].y = fma2(pp0, v1.y, acc[0][1].y);
        acc[1][0].x = fma2(pp1, v0.x, acc[1][0].x);
        acc[1][0].y = fma2(pp1, v0.y, acc[1][0].y);
        acc[1][1].x = fma2(pp1, v1.x, acc[1][1].x);
        acc[1][1].y = fma2(pp1, v1.y, acc[1][1].y);
        acc[2][0].x = fma2(pp2, v0.x, acc[2][0].x);
        acc[2][0].y = fma2(pp2, v0.y, acc[2][0].y);
        acc[2][1].x = fma2(pp2, v1.x, acc[2][1].x);
        acc[2][1].y = fma2(pp2, v1.y, acc[2][1].y);
        acc[3][0].x = fma2(pp3, v0.x, acc[3][0].x);
        acc[3][0].y = fma2(pp3, v0.y, acc[3][0].y);
        acc[3][1].x = fma2(pp3, v1.x, acc[3][1].x);
        acc[3][1].y = fma2(pp3, v1.y, acc[3][1].y);
        v0 = v0n;
        v1 = v1n;
    }

    ulonglong2* obase = reinterpret_cast<ulonglong2*>(
        out_vals + ((size_t)b * S_LEN + base + lq0) * D_DIM);
    #pragma unroll
    for (int q = 0; q < QW; ++q) {
        obase[q * D4 + 2 * lane]     = acc[q][0];
        obase[q * D4 + 2 * lane + 1] = acc[q][1];
    }
}

extern "C" void kernel_launch(void* const* d_in, const int* in_sizes, int n_in,
                              void* d_out, int out_size)
{
    const float* q    = (const float*)d_in[0];
    const float* k    = (const float*)d_in[1];
    const float* v    = (const float*)d_in[2];
    const int*   mask = (const int*)d_in[3];

    float* out_vals = (float*)d_out;
    float* out_p    = out_vals + (size_t)B_SZ * S_LEN * D_DIM;

    static bool attr_set = false;
    if (!attr_set) {
        cudaFuncSetAttribute(local_attn_kernel,
                             cudaFuncAttributeMaxDynamicSharedMemorySize,
                             SMEM_BYTES);
        attr_set = true;
    }

    dim3 grid(S_LEN / TILE_Q, B_SZ);   // (32, 4) = 128 CTAs, one wave
    local_attn_kernel<<<grid, THREADS, SMEM_BYTES>>>(q, k, v, mask, out_vals, out_p);
}

// round 11
// speedup vs baseline: 1.4602x; 1.0135x over previous
#include <cuda_runtime.h>
#include <cstddef>
#include <cstdint>

// LocalAttention: B=4, S=2048, D=256, W=33
// out = [values (B,S,D) | p_attn (B,S,W)] as float32

#define S_LEN   2048
#define D_DIM   256
#define B_SZ    4
#define W_SZ    33
#define HALF_W  16
#define TILE_Q  64
#define THREADS 512                // 16 warps
#define QW      4                  // queries per warp
#define ROWS    (TILE_Q + 2*HALF_W)  // 96 K/V rows in smem
#define D4      (D_DIM/4)          // 64 16B-chunks per row
#define NR      (QW + 2*HALF_W)    // 36 rows per warp
#define NW      (THREADS/32)       // 16 warps

// smem: K + V + score partials [NW][NR][4][2] + final p [NW][NR][4] + flags
#define SMEM_BYTES (ROWS*D_DIM*4*2 + NW*NR*8*4 + NW*NR*4*4 + ROWS*4)

typedef unsigned long long ull;

__device__ __forceinline__ ull fma2(ull a, ull b, ull c) {
    ull d;
    asm("fma.rn.f32x2 %0, %1, %2, %3;" : "=l"(d) : "l"(a), "l"(b), "l"(c));
    return d;
}
__device__ __forceinline__ float f32x2_sum(ull v) {
    float lo, hi;
    asm("mov.b64 {%0, %1}, %2;" : "=f"(lo), "=f"(hi) : "l"(v));
    return lo + hi;
}
__device__ __forceinline__ ull pack2(float x) {
    ull d;
    asm("mov.b64 %0, {%1, %1};" : "=l"(d) : "f"(x));
    return d;
}
__device__ __forceinline__ void cp16(void* smem_dst, const void* gsrc) {
    uint32_t s = (uint32_t)__cvta_generic_to_shared(smem_dst);
    asm volatile("cp.async.cg.shared.global [%0], [%1], 16;" :: "r"(s), "l"(gsrc));
}

__global__ void __launch_bounds__(THREADS, 1)
local_attn_kernel(const float* __restrict__ qg,
                  const float* __restrict__ kg,
                  const float* __restrict__ vg,
                  const int*   __restrict__ maskg,
                  float* __restrict__ out_vals,
                  float* __restrict__ out_p)
{
    extern __shared__ float smem[];
    float4* Ksm = reinterpret_cast<float4*>(smem);
    float4* Vsm = Ksm + ROWS * D4;
    float*  S2P = reinterpret_cast<float*>(Vsm + ROWS * D4);   // [NW][NR][4][2]
    float*  PF  = S2P + NW * NR * 8;                           // [NW][NR][4]
    int*    Fsm = reinterpret_cast<int*>(PF + NW * NR * 4);    // [ROWS]

    const int tile = blockIdx.x;
    const int b    = blockIdx.y;
    const int base = tile * TILE_Q;
    const int r0   = base - HALF_W;
    const int tid  = threadIdx.x;

    const float4* kg4 = reinterpret_cast<const float4*>(kg + (size_t)b * S_LEN * D_DIM);
    const float4* vg4 = reinterpret_cast<const float4*>(vg + (size_t)b * S_LEN * D_DIM);

    // ---- async-stage K (group 0) ----
    #pragma unroll
    for (int it = 0; it < ROWS * D4 / THREADS; ++it) {   // 12 iters
        int idx  = tid + it * THREADS;
        int row  = idx >> 6;
        int col  = idx & (D4 - 1);
        int grow = r0 + row;
        int gcl  = grow < 0 ? 0 : (grow >= S_LEN ? S_LEN - 1 : grow);
        cp16(Ksm + idx, kg4 + (size_t)gcl * D4 + col);
    }
    asm volatile("cp.async.commit_group;" ::: "memory");

    // ---- async-stage V (group 1; waited before pass 2) ----
    #pragma unroll
    for (int it = 0; it < ROWS * D4 / THREADS; ++it) {
        int idx  = tid + it * THREADS;
        int row  = idx >> 6;
        int col  = idx & (D4 - 1);
        int grow = r0 + row;
        int gcl  = grow < 0 ? 0 : (grow >= S_LEN ? S_LEN - 1 : grow);
        cp16(Vsm + idx, vg4 + (size_t)gcl * D4 + col);
    }
    asm volatile("cp.async.commit_group;" ::: "memory");

    // ---- mask flags (during cp.async flight) ----
    if (tid < ROWS) {
        int grow = r0 + tid;
        int f = 0;
        if (grow >= 0 && grow < S_LEN) f = (maskg[b * S_LEN + grow] != 0);
        Fsm[tid] = f;
    }

    const int warp = tid >> 5;
    const int lane = tid & 31;
    const int lq0  = warp * QW;
    float* s2p = S2P + warp * NR * 8;    // this warp's partials [NR][4][2]
    float* pf  = PF  + warp * NR * 4;    // this warp's final p  [NR][4]

    // zero final-p block (out-of-window slots read by pass 2 must be 0)
    #pragma unroll
    for (int i = lane; i < NR * 4; i += 32) pf[i] = 0.f;

    // pass-1 lane decomposition: h = row of pair, p = 16-lane d-position
    const int h  = lane >> 4;
    const int p  = lane & 15;
    const int b3 = (p >> 3) & 1;
    const int b2 = (p >> 2) & 1;
    const int qcar = (b2 << 1) | b3;          // query this lane carries after reduce

    // ---- Q fragments (LDG overlaps the cp.async drain) ----
    ulonglong2 qf[QW][4];
    {
        const ulonglong2* qb = reinterpret_cast<const ulonglong2*>(
            qg + ((size_t)b * S_LEN + base + lq0) * D_DIM);
        #pragma unroll
        for (int q = 0; q < QW; ++q)
            #pragma unroll
            for (int c = 0; c < 4; ++c)
                qf[q][c] = qb[q * D4 + p + 16 * c];
    }

    // wait for K (V still in flight), then block-sync
    asm volatile("cp.async.wait_group 1;" ::: "memory");
    __syncthreads();

    const ulonglong2* Ksm2 = reinterpret_cast<const ulonglong2*>(Ksm);

    // ---- pass 1: 2 rows/iter, K double-buffered, 3-level reduce to 2 partials ----
    ulonglong2 k0, k1, k2, k3;
    {
        const ulonglong2* krow = Ksm2 + (size_t)(lq0 + h) * D4 + p;
        k0 = krow[0]; k1 = krow[16]; k2 = krow[32]; k3 = krow[48];
    }
    #pragma unroll 2
    for (int ri = 0; ri < NR / 2; ++ri) {   // 18 iters
        // prefetch next row pair
        ulonglong2 n0, n1, n2, n3;
        if (ri + 1 < NR / 2) {
            const ulonglong2* kn = Ksm2 + (size_t)(lq0 + 2 * (ri + 1) + h) * D4 + p;
            n0 = kn[0]; n1 = kn[16]; n2 = kn[32]; n3 = kn[48];
        }

        float s[QW];
        #pragma unroll
        for (int q = 0; q < QW; ++q) {
            ull a0 = fma2(k0.x, qf[q][0].x, 0ull);
            ull a1 = fma2(k0.y, qf[q][0].y, 0ull);
            a0 = fma2(k1.x, qf[q][1].x, a0);
            a1 = fma2(k1.y, qf[q][1].y, a1);
            a0 = fma2(k2.x, qf[q][2].x, a0);
            a1 = fma2(k2.y, qf[q][2].y, a1);
            a0 = fma2(k3.x, qf[q][3].x, a0);
            a1 = fma2(k3.y, qf[q][3].y, a1);
            s[q] = f32x2_sum(a0) + f32x2_sum(a1);
        }

        // level xor8 (bit3): pair (s0,s1) and (s2,s3)
        float xA_keep = b3 ? s[1] : s[0];
        float xA_send = b3 ? s[0] : s[1];
        float xB_keep = b3 ? s[3] : s[2];
        float xB_send = b3 ? s[2] : s[3];
        float xA = xA_keep + __shfl_xor_sync(0xffffffffu, xA_send, 8);
        float xB = xB_keep + __shfl_xor_sync(0xffffffffu, xB_send, 8);
        // level xor4 (bit2): pair (xA, xB) -> query qcar over 4 lanes
        float z_keep = b2 ? xB : xA;
        float z_send = b2 ? xA : xB;
        float z = z_keep + __shfl_xor_sync(0xffffffffu, z_send, 4);
        // level xor2: query qcar over 8 lanes -> 2 remaining partials (p&1)
        z += __shfl_xor_sync(0xffffffffu, z, 2);

        int rl = 2 * ri + h;
        int wpos = rl - qcar;
        if ((p & 2) == 0 && wpos >= 0 && wpos < W_SZ) {
            s2p[rl * 8 + qcar * 2 + (p & 1)] = z;   // raw partial (scale+mask later)
        }

        k0 = n0; k1 = n1; k2 = n2; k3 = n3;
    }
    __syncwarp();

    // ---- warp-local softmax: 8 lanes per query; sum partials + scale + mask here ----
    const int g8 = lane >> 3;
    const int j  = lane & 7;
    const int gq = base + lq0 + g8;
    {
        const float* pb = s2p + g8 * 2;
        int m0 = g8 + j;
        float s0 = Fsm[lq0 + m0]      ? (pb[m0 * 8] + pb[m0 * 8 + 1]) * 0.0625f : -1e10f;
        float s1 = Fsm[lq0 + m0 + 8]  ? (pb[(m0 + 8) * 8] + pb[(m0 + 8) * 8 + 1]) * 0.0625f : -1e10f;
        float s2 = Fsm[lq0 + m0 + 16] ? (pb[(m0 + 16) * 8] + pb[(m0 + 16) * 8 + 1]) * 0.0625f : -1e10f;
        float s3 = Fsm[lq0 + m0 + 24] ? (pb[(m0 + 24) * 8] + pb[(m0 + 24) * 8 + 1]) * 0.0625f : -1e10f;
        float s4 = -3e38f;
        if (j == 0) {
            int m4 = g8 + 32;
            s4 = Fsm[lq0 + m4] ? (pb[m4 * 8] + pb[m4 * 8 + 1]) * 0.0625f : -1e10f;
        }

        float mx = fmaxf(fmaxf(fmaxf(s0, s1), fmaxf(s2, s3)), s4);
        mx = fmaxf(mx, __shfl_xor_sync(0xffffffffu, mx, 4));
        mx = fmaxf(mx, __shfl_xor_sync(0xffffffffu, mx, 2));
        mx = fmaxf(mx, __shfl_xor_sync(0xffffffffu, mx, 1));

        float e0 = __expf(s0 - mx);
        float e1 = __expf(s1 - mx);
        float e2 = __expf(s2 - mx);
        float e3 = __expf(s3 - mx);
        float e4 = (j == 0) ? __expf(s4 - mx) : 0.f;

        float sum = ((e0 + e1) + (e2 + e3)) + e4;
        sum += __shfl_xor_sync(0xffffffffu, sum, 4);
        sum += __shfl_xor_sync(0xffffffffu, sum, 2);
        sum += __shfl_xor_sync(0xffffffffu, sum, 1);
        float inv = 1.f / sum;

        float p0 = e0 * inv, p1 = e1 * inv, p2 = e2 * inv, p3 = e3 * inv;
        pf[m0 * 4 + g8]        = p0;
        pf[(m0 + 8) * 4 + g8]  = p1;
        pf[(m0 + 16) * 4 + g8] = p2;
        pf[(m0 + 24) * 4 + g8] = p3;

        float* po = out_p + (size_t)(b * S_LEN + gq) * W_SZ;
        po[j]      = p0;
        po[j + 8]  = p1;
        po[j + 16] = p2;
        po[j + 24] = p3;
        if (j == 0) {
            float p4 = e4 * inv;
            pf[(g8 + 32) * 4 + g8] = p4;
            po[32] = p4;
        }
    }

    // V resident + visible block-wide before pass 2
    asm volatile("cp.async.wait_group 0;" ::: "memory");
    __syncthreads();

    // ---- pass 2: V rows + p float4 both prefetched ----
    ulonglong2 acc[QW][2];
    #pragma unroll
    for (int q = 0; q < QW; ++q) {
        acc[q][0].x = 0ull; acc[q][0].y = 0ull;
        acc[q][1].x = 0ull; acc[q][1].y = 0ull;
    }

    const ulonglong2* Vsm2 = reinterpret_cast<const ulonglong2*>(Vsm);
    const float4* pf4 = reinterpret_cast<const float4*>(pf);

    ulonglong2 v0 = Vsm2[(size_t)lq0 * D4 + 2 * lane];
    ulonglong2 v1 = Vsm2[(size_t)lq0 * D4 + 2 * lane + 1];
    float4 pv = pf4[0];

    #pragma unroll 4
    for (int r = 0; r < NR; ++r) {   // 36
        ulonglong2 v0n, v1n;
        float4 pvn;
        if (r + 1 < NR) {
            const ulonglong2* vn = Vsm2 + (size_t)(lq0 + r + 1) * D4 + 2 * lane;
            v0n = vn[0];
            v1n = vn[1];
            pvn = pf4[r + 1];
        }
        ull pp0 = pack2(pv.x);
        ull pp1 = pack2(pv.y);
        ull pp2 = pack2(pv.z);
        ull pp3 = pack2(pv.w);
        acc[0][0].x = fma2(pp0, v0.x, acc[0][0].x);
        acc[0][0].y = fma2(pp0, v0.y, acc[0][0].y);
        acc[0][1].x = fma2(pp0, v1.x, acc[0][1].x);
        acc[0][1].y = fma2(pp0, v1.y, acc[0][1].y);
        acc[1][0].x = fma2(pp1, v0.x, acc[1][0].x);
        acc[1][0].y = fma2(pp1, v0.y, acc[1][0].y);
        acc[1][1].x = fma2(pp1, v1.x, acc[1][1].x);
        acc[1][1].y = fma2(pp1, v1.y, acc[1][1].y);
        acc[2][0].x = fma2(pp2, v0.x, acc[2][0].x);
        acc[2][0].y = fma2(pp2, v0.y, acc[2][0].y);
        acc[2][1].x = fma2(pp2, v1.x, acc[2][1].x);
        acc[2][1].y = fma2(pp2, v1.y, acc[2][1].y);
        acc[3][0].x = fma2(pp3, v0.x, acc[3][0].x);
        acc[3][0].y = fma2(pp3, v0.y, acc[3][0].y);
        acc[3][1].x = fma2(pp3, v1.x, acc[3][1].x);
        acc[3][1].y = fma2(pp3, v1.y, acc[3][1].y);
        v0 = v0n;
        v1 = v1n;
        pv = pvn;
    }

    ulonglong2* obase = reinterpret_cast<ulonglong2*>(
        out_vals + ((size_t)b * S_LEN + base + lq0) * D_DIM);
    #pragma unroll
    for (int q = 0; q < QW; ++q) {
        obase[q * D4 + 2 * lane]     = acc[q][0];
        obase[q * D4 + 2 * lane + 1] = acc[q][1];
    }
}

extern "C" void kernel_launch(void* const* d_in, const int* in_sizes, int n_in,
                              void* d_out, int out_size)
{
    const float* q    = (const float*)d_in[0];
    const float* k    = (const float*)d_in[1];
    const float* v    = (const float*)d_in[2];
    const int*   mask = (const int*)d_in[3];

    float* out_vals = (float*)d_out;
    float* out_p    = out_vals + (size_t)B_SZ * S_LEN * D_DIM;

    static bool attr_set = false;
    if (!attr_set) {
        cudaFuncSetAttribute(local_attn_kernel,
                             cudaFuncAttributeMaxDynamicSharedMemorySize,
                             SMEM_BYTES);
        attr_set = true;
    }

    dim3 grid(S_LEN / TILE_Q, B_SZ);   // (32, 4) = 128 CTAs, one wave
    local_attn_kernel<<<grid, THREADS, SMEM_BYTES>>>(q, k, v, mask, out_vals, out_p);
}